// round 3
// baseline (speedup 1.0000x reference)
#include <cuda_runtime.h>
#include <math.h>

#define BB   128
#define TT   25
#define VV   10000
#define EE   512
#define NFE  2048
#define HH   512
#define MAPS 512
#define IN0  1024   // EE + MAPS

// ---------------- scratch (device globals; no allocation allowed) ----------------
__device__ float g_p[BB * MAPS];                 // input-layer output
__device__ float g_X0[TT * BB * 1536];           // precomputed x@W (u|r|c) + biases
__device__ float g_h0[2][BB * HH];               // double-buffered layer-0 hidden
__device__ float g_h1[2][BB * HH];               // double-buffered layer-1 hidden
__device__ float g_ur0[BB * 1024];               // layer-0 gates u|r
__device__ float g_ur1[BB * 1024];               // layer-1 gates u|r
__device__ float g_H1[TT * BB * HH];             // all h1_t for logits GEMM
__device__ float g_Whur0[HH * 1024];             // packed [Wu0_h | Wr0_h]
__device__ float g_Wur1[1024 * 1024];            // packed [Wu1 | Wr1]
__device__ float g_bur1[1024];                   // packed [bu1 | br1]

__device__ __forceinline__ float sigmoidf(float x) { return 1.f / (1.f + expf(-x)); }

// ---------------- init / pack ----------------
__global__ void k_zero() {
    int i = blockIdx.x * blockDim.x + threadIdx.x;
    if (i < BB * HH) { g_h0[0][i] = 0.f; g_h1[0][i] = 0.f; }
}

__global__ void k_pack(const float* __restrict__ Wu0, const float* __restrict__ Wr0,
                       const float* __restrict__ Wu1, const float* __restrict__ Wr1,
                       const float* __restrict__ bu1, const float* __restrict__ br1) {
    int i = blockIdx.x * blockDim.x + threadIdx.x;
    if (i < 512 * 1024) {
        int k = i >> 10, n = i & 1023;
        // h-part of Wu0/Wr0 = rows IN0..IN0+H-1  (xh = [x, h])
        g_Whur0[i] = (n < 512) ? Wu0[(IN0 + k) * HH + n] : Wr0[(IN0 + k) * HH + (n - 512)];
        return;
    }
    int j = i - 512 * 1024;
    if (j >= 0 && j < 1024 * 1024) {
        int k = j >> 10, n = j & 1023;
        g_Wur1[j] = (n < 512) ? Wu1[k * HH + n] : Wr1[k * HH + (n - 512)];
        return;
    }
    int m = i - 512 * 1024 - 1024 * 1024;
    if (m >= 0 && m < 1024) g_bur1[m] = (m < 512) ? bu1[m] : br1[m - 512];
}

// ---------------- generic small GEMM (M=128 recurrent phases), 32x32 tiles ----------------
template <int K, typename Op>
__global__ void __launch_bounds__(256) small_gemm(Op op) {
    __shared__ float As[32][33];
    __shared__ float Bs[32][33];
    const int tid = threadIdx.x;
    const int r0 = tid >> 4;     // 0..15
    const int c0 = tid & 15;     // 0..15
    const int mBase = blockIdx.y * 32;
    const int nBase = blockIdx.x * 32;

    float a00 = 0.f, a01 = 0.f, a10 = 0.f, a11 = 0.f;

    for (int k0 = 0; k0 < K; k0 += 32) {
#pragma unroll
        for (int i = 0; i < 4; i++) {
            int e = tid + i * 256;
            int r = e >> 5, kk = e & 31;
            As[r][kk] = op.loadA(mBase + r, k0 + kk);
        }
#pragma unroll
        for (int i = 0; i < 4; i++) {
            int e = tid + i * 256;
            int kk = e >> 5, n = e & 31;
            Bs[kk][n] = op.loadB(k0 + kk, nBase + n);
        }
        __syncthreads();
#pragma unroll
        for (int kk = 0; kk < 32; kk++) {
            float x0 = As[r0][kk],      x1 = As[r0 + 16][kk];
            float y0 = Bs[kk][c0],      y1 = Bs[kk][c0 + 16];
            a00 += x0 * y0; a01 += x0 * y1;
            a10 += x1 * y0; a11 += x1 * y1;
        }
        __syncthreads();
    }
    op.store(mBase + r0,      nBase + c0,      a00);
    op.store(mBase + r0,      nBase + c0 + 16, a01);
    op.store(mBase + r0 + 16, nBase + c0,      a10);
    op.store(mBase + r0 + 16, nBase + c0 + 16, a11);
}

// ----- phase ops -----
struct OpP {  // p = leaky_relu(cnn @ Win + bin)
    const float* A; const float* Bw; const float* bias;
    __device__ float loadA(int r, int k) const { return A[r * NFE + k]; }
    __device__ float loadB(int k, int n) const { return Bw[k * MAPS + n]; }
    __device__ void store(int r, int n, float acc) const {
        float v = acc + bias[n];
        g_p[r * MAPS + n] = v > 0.f ? v : 0.01f * v;
    }
};

struct OpA {  // ur0 = sigmoid(h0 @ Whur0 + X0[u|r])
    int t, cur;
    __device__ float loadA(int r, int k) const { return g_h0[cur][r * HH + k]; }
    __device__ float loadB(int k, int n) const { return g_Whur0[k * 1024 + n]; }
    __device__ void store(int r, int n, float acc) const {
        g_ur0[r * 1024 + n] = sigmoidf(acc + g_X0[(t * BB + r) * 1536 + n]);
    }
};

struct OpB {  // h0' = u*h0 + (1-u)*tanh((r.h0)@Wc0_h + X0[c])
    int t, cur; const float* Wc0;
    __device__ float loadA(int r, int k) const {
        return g_ur0[r * 1024 + 512 + k] * g_h0[cur][r * HH + k];
    }
    __device__ float loadB(int k, int n) const { return Wc0[k * HH + n]; }  // rows 0..511 = r*h part
    __device__ void store(int r, int n, float acc) const {
        float hh = tanhf(acc + g_X0[(t * BB + r) * 1536 + 1024 + n]);
        float u = g_ur0[r * 1024 + n];
        g_h0[cur ^ 1][r * HH + n] = u * g_h0[cur][r * HH + n] + (1.f - u) * hh;
    }
};

struct OpC {  // ur1 = sigmoid([h0', h1] @ Wur1 + b)
    int cur;
    __device__ float loadA(int r, int k) const {
        return (k < HH) ? g_h0[cur ^ 1][r * HH + k] : g_h1[cur][r * HH + (k - HH)];
    }
    __device__ float loadB(int k, int n) const { return g_Wur1[k * 1024 + n]; }
    __device__ void store(int r, int n, float acc) const {
        g_ur1[r * 1024 + n] = sigmoidf(acc + g_bur1[n]);
    }
};

struct OpD {  // h1' = u*h1 + (1-u)*tanh([r1.h1, h0'] @ Wc1 + bc1); also store into H1_all
    int t, cur; const float* Wc1; const float* bc1;
    __device__ float loadA(int r, int k) const {
        return (k < HH) ? g_ur1[r * 1024 + 512 + k] * g_h1[cur][r * HH + k]
                        : g_h0[cur ^ 1][r * HH + (k - HH)];
    }
    __device__ float loadB(int k, int n) const { return Wc1[k * HH + n]; }
    __device__ void store(int r, int n, float acc) const {
        float hh = tanhf(acc + bc1[n]);
        float u = g_ur1[r * 1024 + n];
        float v = u * g_h1[cur][r * HH + n] + (1.f - u) * hh;
        g_h1[cur ^ 1][r * HH + n] = v;
        g_H1[(t * BB + r) * HH + n] = v;
    }
};

// ---------------- precompute X0 = [x@Wu0_x | x@Wr0_x | x@Wc0_x] + biases ----------------
// M = T*B = 3200 (gathered A = [emb[token], p]), K = 1024, N = 1536. 64x64x16 tiles.
// tokens are INT32 (JAX x64 disabled: jnp.int64 silently becomes int32).
__global__ void __launch_bounds__(256) k_precompute(
    const int* __restrict__ tokens, const float* __restrict__ emb,
    const float* __restrict__ Wu0, const float* __restrict__ Wr0, const float* __restrict__ Wc0,
    const float* __restrict__ bu0, const float* __restrict__ br0, const float* __restrict__ bc0)
{
    __shared__ float As[64][17];
    __shared__ float Bs[16][64];
    const int tid = threadIdx.x;
    const int mBase = blockIdx.y * 64;
    const int nBase = blockIdx.x * 64;
    const int region = nBase >> 9;                   // 0:u, 1:r, 2:c (tile never straddles)
    const float* Bw   = (region == 0) ? Wu0 : (region == 1) ? Wr0 : Wc0;
    const float* bias = (region == 0) ? bu0 : (region == 1) ? br0 : bc0;
    const int row0 = (region == 2) ? 512 : 0;        // x-part of Wc0 = rows 512..1535 ([r*h, x])
    const int nOff = nBase - region * 512;

    const int r0 = tid >> 4, c0 = tid & 15;

    // per-thread A rows are fixed across the K loop
    const int rl = tid >> 4;          // 0..15, rows rl + {0,16,32,48}
    const int kl = tid & 15;          // column within BK
    int tok[4]; int bidx[4];
#pragma unroll
    for (int i = 0; i < 4; i++) {
        int m = mBase + rl + 16 * i;
        bidx[i] = m & 127;            // batch index
        tok[i] = tokens[bidx[i] * TT + (m >> 7)];   // tokens[b][t]
    }

    float acc[4][4];
#pragma unroll
    for (int i = 0; i < 4; i++)
#pragma unroll
        for (int j = 0; j < 4; j++) acc[i][j] = 0.f;

    for (int k0 = 0; k0 < IN0; k0 += 16) {
        int kabs = k0 + kl;
#pragma unroll
        for (int i = 0; i < 4; i++) {
            float v = (kabs < 512) ? emb[(size_t)tok[i] * EE + kabs]
                                   : g_p[bidx[i] * MAPS + (kabs - 512)];
            As[rl + 16 * i][kl] = v;
        }
#pragma unroll
        for (int i = 0; i < 4; i++) {
            int e = tid + i * 256;
            int kk = e >> 6, n = e & 63;
            Bs[kk][n] = Bw[(row0 + k0 + kk) * HH + nOff + n];
        }
        __syncthreads();
#pragma unroll
        for (int kk = 0; kk < 16; kk++) {
            float a0 = As[r0][kk], a1 = As[r0 + 16][kk], a2 = As[r0 + 32][kk], a3 = As[r0 + 48][kk];
            float b0 = Bs[kk][c0], b1 = Bs[kk][c0 + 16], b2 = Bs[kk][c0 + 32], b3 = Bs[kk][c0 + 48];
            acc[0][0] += a0 * b0; acc[0][1] += a0 * b1; acc[0][2] += a0 * b2; acc[0][3] += a0 * b3;
            acc[1][0] += a1 * b0; acc[1][1] += a1 * b1; acc[1][2] += a1 * b2; acc[1][3] += a1 * b3;
            acc[2][0] += a2 * b0; acc[2][1] += a2 * b1; acc[2][2] += a2 * b2; acc[2][3] += a2 * b3;
            acc[3][0] += a3 * b0; acc[3][1] += a3 * b1; acc[3][2] += a3 * b2; acc[3][3] += a3 * b3;
        }
        __syncthreads();
    }
#pragma unroll
    for (int i = 0; i < 4; i++) {
        int m = mBase + r0 + 16 * i;
#pragma unroll
        for (int j = 0; j < 4; j++) {
            int nl = nOff + c0 + 16 * j;
            g_X0[m * 1536 + nBase + c0 + 16 * j] = acc[i][j] + bias[nl];
        }
    }
}

// ---------------- logits = H1_all @ Wout + bout ; out[b][t][v] ----------------
__global__ void __launch_bounds__(256) k_logits(const float* __restrict__ Wout,
                                                const float* __restrict__ bout,
                                                float* __restrict__ out)
{
    __shared__ float As[64][17];
    __shared__ float Bs[16][64];
    const int tid = threadIdx.x;
    const int mBase = blockIdx.y * 64;
    const int nBase = blockIdx.x * 64;
    const int r0 = tid >> 4, c0 = tid & 15;
    const int rl = tid >> 4, kl = tid & 15;

    float acc[4][4];
#pragma unroll
    for (int i = 0; i < 4; i++)
#pragma unroll
        for (int j = 0; j < 4; j++) acc[i][j] = 0.f;

    for (int k0 = 0; k0 < HH; k0 += 16) {
#pragma unroll
        for (int i = 0; i < 4; i++)
            As[rl + 16 * i][kl] = g_H1[(mBase + rl + 16 * i) * HH + k0 + kl];
#pragma unroll
        for (int i = 0; i < 4; i++) {
            int e = tid + i * 256;
            int kk = e >> 6, n = e & 63;
            int col = nBase + n;
            Bs[kk][n] = (col < VV) ? Wout[(k0 + kk) * VV + col] : 0.f;
        }
        __syncthreads();
#pragma unroll
        for (int kk = 0; kk < 16; kk++) {
            float a0 = As[r0][kk], a1 = As[r0 + 16][kk], a2 = As[r0 + 32][kk], a3 = As[r0 + 48][kk];
            float b0 = Bs[kk][c0], b1 = Bs[kk][c0 + 16], b2 = Bs[kk][c0 + 32], b3 = Bs[kk][c0 + 48];
            acc[0][0] += a0 * b0; acc[0][1] += a0 * b1; acc[0][2] += a0 * b2; acc[0][3] += a0 * b3;
            acc[1][0] += a1 * b0; acc[1][1] += a1 * b1; acc[1][2] += a1 * b2; acc[1][3] += a1 * b3;
            acc[2][0] += a2 * b0; acc[2][1] += a2 * b1; acc[2][2] += a2 * b2; acc[2][3] += a2 * b3;
            acc[3][0] += a3 * b0; acc[3][1] += a3 * b1; acc[3][2] += a3 * b2; acc[3][3] += a3 * b3;
        }
        __syncthreads();
    }
#pragma unroll
    for (int i = 0; i < 4; i++) {
        int m = mBase + r0 + 16 * i;
        int tIdx = m >> 7, b = m & 127;
        size_t rowOff = ((size_t)b * TT + tIdx) * VV;
#pragma unroll
        for (int j = 0; j < 4; j++) {
            int col = nBase + c0 + 16 * j;
            if (col < VV) out[rowOff + col] = acc[i][j] + bout[col];
        }
    }
}

__global__ void k_hidden(float* __restrict__ outh) {
    int i = blockIdx.x * blockDim.x + threadIdx.x;
    if (i < BB * HH) {
        outh[i]           = g_h0[1][i];   // after 25 steps (t=24, cur=0), final state is buffer 1
        outh[BB * HH + i] = g_h1[1][i];
    }
}

// ---------------- launch ----------------
extern "C" void kernel_launch(void* const* d_in, const int* in_sizes, int n_in,
                              void* d_out, int out_size) {
    const int*   tokens = (const int*)d_in[0];     // int32! (JAX x64 disabled)
    const float* cnn  = (const float*)d_in[1];
    const float* emb  = (const float*)d_in[2];
    const float* Win  = (const float*)d_in[3];
    const float* bin  = (const float*)d_in[4];
    const float* Wout = (const float*)d_in[5];
    const float* bout = (const float*)d_in[6];
    const float* Wu0  = (const float*)d_in[7];
    const float* bu0  = (const float*)d_in[8];
    const float* Wr0  = (const float*)d_in[9];
    const float* br0  = (const float*)d_in[10];
    const float* Wc0  = (const float*)d_in[11];
    const float* bc0  = (const float*)d_in[12];
    const float* Wu1  = (const float*)d_in[13];
    const float* bu1  = (const float*)d_in[14];
    const float* Wr1  = (const float*)d_in[15];
    const float* br1  = (const float*)d_in[16];
    const float* Wc1  = (const float*)d_in[17];
    const float* bc1  = (const float*)d_in[18];
    float* out = (float*)d_out;

    k_zero<<<(BB * HH + 255) / 256, 256>>>();
    k_pack<<<(512 * 1024 + 1024 * 1024 + 1024 + 255) / 256, 256>>>(Wu0, Wr0, Wu1, Wr1, bu1, br1);

    // input layer: p = leaky_relu(cnn @ Win + bin)   [128,2048]x[2048,512]
    small_gemm<NFE, OpP><<<dim3(MAPS / 32, BB / 32), 256>>>(OpP{cnn, Win, bin});

    // precompute x-dependent GRU0 terms for all timesteps  [3200,1024]x[1024,1536]
    k_precompute<<<dim3(1536 / 64, (TT * BB) / 64), 256>>>(tokens, emb, Wu0, Wr0, Wc0, bu0, br0, bc0);

    // sequential recurrence: 4 small GEMMs per step, activations fused
    for (int t = 0; t < TT; t++) {
        int cur = t & 1;
        small_gemm<HH,   OpA><<<dim3(1024 / 32, BB / 32), 256>>>(OpA{t, cur});
        small_gemm<HH,   OpB><<<dim3(HH   / 32, BB / 32), 256>>>(OpB{t, cur, Wc0});
        small_gemm<1024, OpC><<<dim3(1024 / 32, BB / 32), 256>>>(OpC{cur});
        small_gemm<1024, OpD><<<dim3(HH   / 32, BB / 32), 256>>>(OpD{t, cur, Wc1, bc1});
    }

    // logits: [3200,512] x [512,10000] + bias, written as [B,T,V]
    k_logits<<<dim3((VV + 63) / 64, (TT * BB) / 64), 256>>>(Wout, bout, out);

    // hidden [2,B,H] appended after logits
    k_hidden<<<(BB * HH + 255) / 256, 256>>>(out + (size_t)BB * TT * VV);
}

// round 4
// speedup vs baseline: 1.0094x; 1.0094x over previous
#include <cuda_runtime.h>
#include <math.h>

#define BB   128
#define TT   25
#define VV   10000
#define EE   512
#define NFE  2048
#define HH   512
#define MAPS 512
#define IN0  1024   // EE + MAPS
#define NBLK 128    // persistent recurrence grid (must be <= 148 for co-residency)

// ---------------- scratch (device globals; no allocation allowed) ----------------
__device__ float g_p[BB * MAPS];                 // input-layer output
__device__ float g_X0[TT * BB * 1536];           // precomputed x@W (u|r|c) + biases
__device__ float g_h0[2][BB * HH];               // double-buffered layer-0 hidden
__device__ float g_h1[2][BB * HH];               // double-buffered layer-1 hidden
__device__ float g_ur0[BB * 1024];               // layer-0 gates u|r
__device__ float g_ur1[BB * 1024];               // layer-1 gates u|r
__device__ float g_H1[TT * BB * HH];             // all h1_t for logits GEMM
__device__ float g_bur1[1024];                   // packed [bu1 | br1]

// transposed recurrent weights, [n][k] layout for coalesced staging
__device__ float g_WAT[1024 * 512];              // [Wu0_h | Wr0_h]^T   n<1024, k<512
__device__ float g_WBT[512 * 512];               // Wc0 h-part ^T       n<512,  k<512
__device__ float g_WCT[1024 * 1024];             // [Wu1 | Wr1]^T       n<1024, k<1024
__device__ float g_WDT[512 * 1024];              // Wc1 ^T              n<512,  k<1024

// device-wide barrier state (reset by k_pack each launch)
__device__ int g_bar_arrive;
__device__ int g_bar_epoch;

__device__ __forceinline__ float sigmoidf(float x) { return 1.f / (1.f + expf(-x)); }
__device__ __forceinline__ float4 ldcg4(const float* p) {
    return __ldcg(reinterpret_cast<const float4*>(p));
}

__device__ __forceinline__ void gbar(int e) {
    __syncthreads();
    if (threadIdx.x == 0) {
        __threadfence();
        if (atomicAdd(&g_bar_arrive, 1) == NBLK - 1) {
            g_bar_arrive = 0;
            __threadfence();
            atomicExch(&g_bar_epoch, e);
        } else {
            while (atomicAdd(&g_bar_epoch, 0) < e) { }
        }
        __threadfence();
    }
    __syncthreads();
}

// ---------------- pack: transpose recurrent weights + bias pack + barrier reset ----------------
__global__ void k_pack(const float* __restrict__ Wu0, const float* __restrict__ Wr0,
                       const float* __restrict__ Wc0,
                       const float* __restrict__ Wu1, const float* __restrict__ Wr1,
                       const float* __restrict__ Wc1,
                       const float* __restrict__ bu1, const float* __restrict__ br1) {
    long long i = (long long)blockIdx.x * blockDim.x + threadIdx.x;
    if (i == 0) { g_bar_arrive = 0; g_bar_epoch = 0; }
    // WAT: 1024x512  (h-part of Wu0|Wr0: rows IN0..IN0+511 of W[(H+IN0) x H])
    if (i < 1024LL * 512) {
        int n = (int)(i >> 9), k = (int)(i & 511);
        g_WAT[i] = (n < 512) ? Wu0[(IN0 + k) * HH + n] : Wr0[(IN0 + k) * HH + (n - 512)];
        return;
    }
    i -= 1024LL * 512;
    // WBT: 512x512 (Wc0 rows 0..511 = r*h part)
    if (i < 512LL * 512) {
        int n = (int)(i >> 9), k = (int)(i & 511);
        g_WBT[i] = Wc0[k * HH + n];
        return;
    }
    i -= 512LL * 512;
    // WCT: 1024x1024 ([Wu1|Wr1], K=1024)
    if (i < 1024LL * 1024) {
        int n = (int)(i >> 10), k = (int)(i & 1023);
        g_WCT[i] = (n < 512) ? Wu1[k * HH + n] : Wr1[k * HH + (n - 512)];
        return;
    }
    i -= 1024LL * 1024;
    // WDT: 512x1024 (Wc1, K=1024)
    if (i < 512LL * 1024) {
        int n = (int)(i >> 10), k = (int)(i & 1023);
        g_WDT[i] = Wc1[k * HH + n];
        return;
    }
    i -= 512LL * 1024;
    if (i < 1024) g_bur1[i] = (i < 512) ? bu1[i] : br1[i - 512];
}

// ---------------- input layer GEMM (unchanged path) ----------------
template <int K, typename Op>
__global__ void __launch_bounds__(256) small_gemm(Op op) {
    __shared__ float As[32][33];
    __shared__ float Bs[32][33];
    const int tid = threadIdx.x;
    const int r0 = tid >> 4;
    const int c0 = tid & 15;
    const int mBase = blockIdx.y * 32;
    const int nBase = blockIdx.x * 32;

    float a00 = 0.f, a01 = 0.f, a10 = 0.f, a11 = 0.f;

    for (int k0 = 0; k0 < K; k0 += 32) {
#pragma unroll
        for (int i = 0; i < 4; i++) {
            int e = tid + i * 256;
            int r = e >> 5, kk = e & 31;
            As[r][kk] = op.loadA(mBase + r, k0 + kk);
        }
#pragma unroll
        for (int i = 0; i < 4; i++) {
            int e = tid + i * 256;
            int kk = e >> 5, n = e & 31;
            Bs[kk][n] = op.loadB(k0 + kk, nBase + n);
        }
        __syncthreads();
#pragma unroll
        for (int kk = 0; kk < 32; kk++) {
            float x0 = As[r0][kk],      x1 = As[r0 + 16][kk];
            float y0 = Bs[kk][c0],      y1 = Bs[kk][c0 + 16];
            a00 += x0 * y0; a01 += x0 * y1;
            a10 += x1 * y0; a11 += x1 * y1;
        }
        __syncthreads();
    }
    op.store(mBase + r0,      nBase + c0,      a00);
    op.store(mBase + r0,      nBase + c0 + 16, a01);
    op.store(mBase + r0 + 16, nBase + c0,      a10);
    op.store(mBase + r0 + 16, nBase + c0 + 16, a11);
}

struct OpP {  // p = leaky_relu(cnn @ Win + bin)
    const float* A; const float* Bw; const float* bias;
    __device__ float loadA(int r, int k) const { return A[r * NFE + k]; }
    __device__ float loadB(int k, int n) const { return Bw[k * MAPS + n]; }
    __device__ void store(int r, int n, float acc) const {
        float v = acc + bias[n];
        g_p[r * MAPS + n] = v > 0.f ? v : 0.01f * v;
    }
};

// ---------------- persistent recurrence ----------------
// One phase: out[128 x COLS] (cols cb..cb+COLS-1 of the phase output), K = KTOT.
// 8 warps: warp w -> rows [(w&3)*32, +32), cols cb + (COLS/2)*(w>>2) .. +COLS/2-1.
template <int PH, int COLS, int KTOT>
__device__ __forceinline__ void run_phase(
    float As[32][129], float Bs[8][36], int t,
    const float* h0c, float* h0n, const float* h1c, float* h1n,
    const float* __restrict__ bc1)
{
    const int tid = threadIdx.x, blk = blockIdx.x;
    const int w = tid >> 5, lane = tid & 31;
    const int row = ((w & 3) << 5) + lane;
    constexpr int CW = COLS / 2;
    const int cb = blk * COLS;
    const int cwl = CW * (w >> 2);          // local col base within block
    const int cg = cb + cwl;                // global col base for this warp

    const int rA = tid >> 1;                // staging row 0..127
    const int kg = (tid & 1) * 16;          // staging k offset within chunk

    const float* WT = (PH == 0) ? g_WAT : (PH == 1) ? g_WBT : (PH == 2) ? g_WCT : g_WDT;

    float acc[CW];
#pragma unroll
    for (int j = 0; j < CW; j++) acc[j] = 0.f;

    // register prefetch buffers
    float4 va[4];
    float4 vb;

    auto loadA = [&](int ka) -> float4 {
        if (PH == 0) {
            return ldcg4(h0c + rA * HH + ka);
        } else if (PH == 1) {
            float4 u = ldcg4(g_ur0 + rA * 1024 + 512 + ka);
            float4 h = ldcg4(h0c + rA * HH + ka);
            return make_float4(u.x * h.x, u.y * h.y, u.z * h.z, u.w * h.w);
        } else if (PH == 2) {
            return (ka < 512) ? ldcg4(h0n + rA * HH + ka)
                              : ldcg4(h1c + rA * HH + (ka - 512));
        } else {
            if (ka < 512) {
                float4 u = ldcg4(g_ur1 + rA * 1024 + 512 + ka);
                float4 h = ldcg4(h1c + rA * HH + ka);
                return make_float4(u.x * h.x, u.y * h.y, u.z * h.z, u.w * h.w);
            }
            return ldcg4(h0n + rA * HH + (ka - 512));
        }
    };

    // prefetch chunk 0
#pragma unroll
    for (int j2 = 0; j2 < 4; j2++) va[j2] = loadA(kg + j2 * 4);
    if (tid < COLS * 8) {
        int c = tid >> 3, kk4 = (tid & 7) * 4;
        vb = *reinterpret_cast<const float4*>(WT + (cb + c) * KTOT + kk4);
    }

    for (int k0 = 0; k0 < KTOT; k0 += 32) {
        // commit prefetched regs to smem
#pragma unroll
        for (int j2 = 0; j2 < 4; j2++) {
            int kk = kg + j2 * 4;
            As[kk][rA]     = va[j2].x;
            As[kk + 1][rA] = va[j2].y;
            As[kk + 2][rA] = va[j2].z;
            As[kk + 3][rA] = va[j2].w;
        }
        if (tid < COLS * 8) {
            int c = tid >> 3, kk4 = (tid & 7) * 4;
            *reinterpret_cast<float4*>(&Bs[c][kk4]) = vb;
        }
        __syncthreads();

        // prefetch next chunk while computing
        if (k0 + 32 < KTOT) {
#pragma unroll
            for (int j2 = 0; j2 < 4; j2++) va[j2] = loadA(k0 + 32 + kg + j2 * 4);
            if (tid < COLS * 8) {
                int c = tid >> 3, kk4 = (tid & 7) * 4;
                vb = *reinterpret_cast<const float4*>(WT + (cb + c) * KTOT + k0 + 32 + kk4);
            }
        }

#pragma unroll
        for (int kk = 0; kk < 32; kk += 2) {
            float a0 = As[kk][row];
            float a1 = As[kk + 1][row];
#pragma unroll
            for (int j = 0; j < CW; j++) {
                float2 b = *reinterpret_cast<const float2*>(&Bs[cwl + j][kk]);
                acc[j] = fmaf(a0, b.x, fmaf(a1, b.y, acc[j]));
            }
        }
        __syncthreads();
    }

    // ---- epilogues ----
    if (PH == 0) {        // ur0 = sigmoid(acc + X0[u|r])
        const float* x = g_X0 + (t * BB + row) * 1536 + cg;
        float4 o;
        o.x = sigmoidf(acc[0] + x[0]);
        o.y = sigmoidf(acc[1] + x[1]);
        o.z = sigmoidf(acc[2] + x[2]);
        o.w = sigmoidf(acc[3] + x[3]);
        *reinterpret_cast<float4*>(g_ur0 + row * 1024 + cg) = o;
    } else if (PH == 1) { // h0' = u*h0 + (1-u)*tanh(acc + X0[c])
        const float* x = g_X0 + (t * BB + row) * 1536 + 1024 + cg;
        float u0 = __ldcg(g_ur0 + row * 1024 + cg);
        float u1 = __ldcg(g_ur0 + row * 1024 + cg + 1);
        float p0 = __ldcg(h0c + row * HH + cg);
        float p1 = __ldcg(h0c + row * HH + cg + 1);
        float hh0 = tanhf(acc[0] + x[0]);
        float hh1 = tanhf(acc[1] + x[1]);
        float2 o;
        o.x = u0 * p0 + (1.f - u0) * hh0;
        o.y = u1 * p1 + (1.f - u1) * hh1;
        *reinterpret_cast<float2*>(h0n + row * HH + cg) = o;
    } else if (PH == 2) { // ur1 = sigmoid(acc + bur1)
        float4 o;
        o.x = sigmoidf(acc[0] + g_bur1[cg]);
        o.y = sigmoidf(acc[1] + g_bur1[cg + 1]);
        o.z = sigmoidf(acc[2] + g_bur1[cg + 2]);
        o.w = sigmoidf(acc[3] + g_bur1[cg + 3]);
        *reinterpret_cast<float4*>(g_ur1 + row * 1024 + cg) = o;
    } else {              // h1' = u*h1 + (1-u)*tanh(acc + bc1); also H1[t]
        float u0 = __ldcg(g_ur1 + row * 1024 + cg);
        float u1 = __ldcg(g_ur1 + row * 1024 + cg + 1);
        float p0 = __ldcg(h1c + row * HH + cg);
        float p1 = __ldcg(h1c + row * HH + cg + 1);
        float hh0 = tanhf(acc[0] + bc1[cg]);
        float hh1 = tanhf(acc[1] + bc1[cg + 1]);
        float2 o;
        o.x = u0 * p0 + (1.f - u0) * hh0;
        o.y = u1 * p1 + (1.f - u1) * hh1;
        *reinterpret_cast<float2*>(h1n + row * HH + cg) = o;
        *reinterpret_cast<float2*>(g_H1 + (t * BB + row) * HH + cg) = o;
    }
}

__global__ void __launch_bounds__(256, 1) k_recurrence(const float* __restrict__ bc1) {
    __shared__ float As[32][129];
    __shared__ float Bs[8][36];
    const int tid = threadIdx.x, blk = blockIdx.x;
    int ep = 0;

    // zero initial states (buffer 0)
    {
        int idx = blk * 256 + tid;            // 0..32767
        g_h0[0][idx] = 0.f; g_h0[0][idx + 32768] = 0.f;
        g_h1[0][idx] = 0.f; g_h1[0][idx + 32768] = 0.f;
    }
    gbar(++ep);

    for (int t = 0; t < TT; t++) {
        const int cur = t & 1;
        const float* h0c = g_h0[cur];
        float*       h0n = g_h0[cur ^ 1];
        const float* h1c = g_h1[cur];
        float*       h1n = g_h1[cur ^ 1];

        run_phase<0, 8,  512>(As, Bs, t, h0c, h0n, h1c, h1n, bc1);  // ur0
        gbar(++ep);
        run_phase<1, 4,  512>(As, Bs, t, h0c, h0n, h1c, h1n, bc1);  // h0'
        gbar(++ep);
        run_phase<2, 8, 1024>(As, Bs, t, h0c, h0n, h1c, h1n, bc1);  // ur1
        gbar(++ep);
        run_phase<3, 4, 1024>(As, Bs, t, h0c, h0n, h1c, h1n, bc1);  // h1'
        gbar(++ep);
    }
}

// ---------------- precompute X0 = [x@Wu0_x | x@Wr0_x | x@Wc0_x] + biases ----------------
__global__ void __launch_bounds__(256) k_precompute(
    const int* __restrict__ tokens, const float* __restrict__ emb,
    const float* __restrict__ Wu0, const float* __restrict__ Wr0, const float* __restrict__ Wc0,
    const float* __restrict__ bu0, const float* __restrict__ br0, const float* __restrict__ bc0)
{
    __shared__ float As[64][17];
    __shared__ float Bs[16][64];
    const int tid = threadIdx.x;
    const int mBase = blockIdx.y * 64;
    const int nBase = blockIdx.x * 64;
    const int region = nBase >> 9;                   // 0:u, 1:r, 2:c
    const float* Bw   = (region == 0) ? Wu0 : (region == 1) ? Wr0 : Wc0;
    const float* bias = (region == 0) ? bu0 : (region == 1) ? br0 : bc0;
    const int row0 = (region == 2) ? 512 : 0;        // x-part of Wc0 = rows 512..1535
    const int nOff = nBase - region * 512;

    const int r0 = tid >> 4, c0 = tid & 15;
    const int rl = tid >> 4, kl = tid & 15;
    int tok[4]; int bidx[4];
#pragma unroll
    for (int i = 0; i < 4; i++) {
        int m = mBase + rl + 16 * i;
        bidx[i] = m & 127;
        tok[i] = tokens[bidx[i] * TT + (m >> 7)];
    }

    float acc[4][4];
#pragma unroll
    for (int i = 0; i < 4; i++)
#pragma unroll
        for (int j = 0; j < 4; j++) acc[i][j] = 0.f;

    for (int k0 = 0; k0 < IN0; k0 += 16) {
        int kabs = k0 + kl;
#pragma unroll
        for (int i = 0; i < 4; i++) {
            float v = (kabs < 512) ? emb[(size_t)tok[i] * EE + kabs]
                                   : g_p[bidx[i] * MAPS + (kabs - 512)];
            As[rl + 16 * i][kl] = v;
        }
#pragma unroll
        for (int i = 0; i < 4; i++) {
            int e = tid + i * 256;
            int kk = e >> 6, n = e & 63;
            Bs[kk][n] = Bw[(row0 + k0 + kk) * HH + nOff + n];
        }
        __syncthreads();
#pragma unroll
        for (int kk = 0; kk < 16; kk++) {
            float a0 = As[r0][kk], a1 = As[r0 + 16][kk], a2 = As[r0 + 32][kk], a3 = As[r0 + 48][kk];
            float b0 = Bs[kk][c0], b1 = Bs[kk][c0 + 16], b2 = Bs[kk][c0 + 32], b3 = Bs[kk][c0 + 48];
            acc[0][0] += a0 * b0; acc[0][1] += a0 * b1; acc[0][2] += a0 * b2; acc[0][3] += a0 * b3;
            acc[1][0] += a1 * b0; acc[1][1] += a1 * b1; acc[1][2] += a1 * b2; acc[1][3] += a1 * b3;
            acc[2][0] += a2 * b0; acc[2][1] += a2 * b1; acc[2][2] += a2 * b2; acc[2][3] += a2 * b3;
            acc[3][0] += a3 * b0; acc[3][1] += a3 * b1; acc[3][2] += a3 * b2; acc[3][3] += a3 * b3;
        }
        __syncthreads();
    }
#pragma unroll
    for (int i = 0; i < 4; i++) {
        int m = mBase + r0 + 16 * i;
#pragma unroll
        for (int j = 0; j < 4; j++) {
            int nl = nOff + c0 + 16 * j;
            g_X0[m * 1536 + nBase + c0 + 16 * j] = acc[i][j] + bias[nl];
        }
    }
}

// ---------------- logits = H1_all @ Wout + bout ; out[b][t][v] ----------------
__global__ void __launch_bounds__(256) k_logits(const float* __restrict__ Wout,
                                                const float* __restrict__ bout,
                                                float* __restrict__ out)
{
    __shared__ float As[64][17];
    __shared__ float Bs[16][64];
    const int tid = threadIdx.x;
    const int mBase = blockIdx.y * 64;
    const int nBase = blockIdx.x * 64;
    const int r0 = tid >> 4, c0 = tid & 15;
    const int rl = tid >> 4, kl = tid & 15;

    float acc[4][4];
#pragma unroll
    for (int i = 0; i < 4; i++)
#pragma unroll
        for (int j = 0; j < 4; j++) acc[i][j] = 0.f;

    for (int k0 = 0; k0 < HH; k0 += 16) {
#pragma unroll
        for (int i = 0; i < 4; i++)
            As[rl + 16 * i][kl] = g_H1[(mBase + rl + 16 * i) * HH + k0 + kl];
#pragma unroll
        for (int i = 0; i < 4; i++) {
            int e = tid + i * 256;
            int kk = e >> 6, n = e & 63;
            int col = nBase + n;
            Bs[kk][n] = (col < VV) ? Wout[(k0 + kk) * VV + col] : 0.f;
        }
        __syncthreads();
#pragma unroll
        for (int kk = 0; kk < 16; kk++) {
            float a0 = As[r0][kk], a1 = As[r0 + 16][kk], a2 = As[r0 + 32][kk], a3 = As[r0 + 48][kk];
            float b0 = Bs[kk][c0], b1 = Bs[kk][c0 + 16], b2 = Bs[kk][c0 + 32], b3 = Bs[kk][c0 + 48];
            acc[0][0] += a0 * b0; acc[0][1] += a0 * b1; acc[0][2] += a0 * b2; acc[0][3] += a0 * b3;
            acc[1][0] += a1 * b0; acc[1][1] += a1 * b1; acc[1][2] += a1 * b2; acc[1][3] += a1 * b3;
            acc[2][0] += a2 * b0; acc[2][1] += a2 * b1; acc[2][2] += a2 * b2; acc[2][3] += a2 * b3;
            acc[3][0] += a3 * b0; acc[3][1] += a3 * b1; acc[3][2] += a3 * b2; acc[3][3] += a3 * b3;
        }
        __syncthreads();
    }
#pragma unroll
    for (int i = 0; i < 4; i++) {
        int m = mBase + r0 + 16 * i;
        int tIdx = m >> 7, b = m & 127;
        size_t rowOff = ((size_t)b * TT + tIdx) * VV;
#pragma unroll
        for (int j = 0; j < 4; j++) {
            int col = nBase + c0 + 16 * j;
            if (col < VV) out[rowOff + col] = acc[i][j] + bout[col];
        }
    }
}

__global__ void k_hidden(float* __restrict__ outh) {
    int i = blockIdx.x * blockDim.x + threadIdx.x;
    if (i < BB * HH) {
        outh[i]           = g_h0[1][i];   // after 25 steps final state is buffer 1
        outh[BB * HH + i] = g_h1[1][i];
    }
}

// ---------------- launch ----------------
extern "C" void kernel_launch(void* const* d_in, const int* in_sizes, int n_in,
                              void* d_out, int out_size) {
    const int*   tokens = (const int*)d_in[0];     // int32 (JAX x64 disabled)
    const float* cnn  = (const float*)d_in[1];
    const float* emb  = (const float*)d_in[2];
    const float* Win  = (const float*)d_in[3];
    const float* bin  = (const float*)d_in[4];
    const float* Wout = (const float*)d_in[5];
    const float* bout = (const float*)d_in[6];
    const float* Wu0  = (const float*)d_in[7];
    const float* bu0  = (const float*)d_in[8];
    const float* Wr0  = (const float*)d_in[9];
    const float* br0  = (const float*)d_in[10];
    const float* Wc0  = (const float*)d_in[11];
    const float* bc0  = (const float*)d_in[12];
    const float* Wu1  = (const float*)d_in[13];
    const float* bu1  = (const float*)d_in[14];
    const float* Wr1  = (const float*)d_in[15];
    const float* br1  = (const float*)d_in[16];
    const float* Wc1  = (const float*)d_in[17];
    const float* bc1  = (const float*)d_in[18];
    float* out = (float*)d_out;

    // pack (weight transposes + biases) + barrier reset
    long long packN = 1024LL*512 + 512LL*512 + 1024LL*1024 + 512LL*1024 + 1024;
    k_pack<<<(int)((packN + 255) / 256), 256>>>(Wu0, Wr0, Wc0, Wu1, Wr1, Wc1, bu1, br1);

    // input layer: p = leaky_relu(cnn @ Win + bin)
    small_gemm<NFE, OpP><<<dim3(MAPS / 32, BB / 32), 256>>>(OpP{cnn, Win, bin});

    // precompute x-dependent GRU0 terms for all timesteps
    k_precompute<<<dim3(1536 / 64, (TT * BB) / 64), 256>>>(tokens, emb, Wu0, Wr0, Wc0, bu0, br0, bc0);

    // whole 25-step recurrence in ONE persistent kernel
    k_recurrence<<<NBLK, 256>>>(bc1);

    // logits: [3200,512] x [512,10000] + bias -> [B,T,V]
    k_logits<<<dim3((VV + 63) / 64, (TT * BB) / 64), 256>>>(Wout, bout, out);

    // hidden [2,B,H]
    k_hidden<<<(BB * HH + 255) / 256, 256>>>(out + (size_t)BB * TT * VV);
}